// round 12
// baseline (speedup 1.0000x reference)
#include <cuda_runtime.h>
#include <cuda_fp16.h>
#include <cstdint>

#define N_NODES_MAX 50000
#define NODE_DIM    128
#define HIDDEN      256
#define NCOLS       1024

// Table column layout: [0:256)=seg0 (p1 row), [256:512)=seg2 (p2 row),
//                      [512:768)=seg1 (p1 col), [768:1024)=seg3 (p2 col)

__device__ __half g_table[(size_t)N_NODES_MAX * NCOLS];   // 102.4 MB
__device__ __half g_Xh[(size_t)N_NODES_MAX * NODE_DIM];   // 12.8 MB
__device__ __half g_WTh[NCOLS * NODE_DIM];                // [n][k] permuted
__device__ __half g_ch[HIDDEN];                           // bias const, half
__device__ __half g_w2h[HIDDEN];                          // W2, half
__device__ int    g_is64;

__device__ __forceinline__ uint32_t smem_u32(const void* p) {
    uint32_t a;
    asm("{ .reg .u64 t; cvta.to.shared.u64 t, %1; cvt.u32.u64 %0, t; }" : "=r"(a) : "l"(p));
    return a;
}
__device__ __forceinline__ void ldsm_x4(uint32_t& r0, uint32_t& r1, uint32_t& r2, uint32_t& r3,
                                        uint32_t addr) {
    asm volatile("ldmatrix.sync.aligned.m8n8.x4.shared.b16 {%0,%1,%2,%3}, [%4];"
                 : "=r"(r0), "=r"(r1), "=r"(r2), "=r"(r3) : "r"(addr));
}
__device__ __forceinline__ void mma16816(float* c, const uint32_t* a, uint32_t b0, uint32_t b1) {
    asm volatile("mma.sync.aligned.m16n8k16.row.col.f32.f16.f16.f32 "
                 "{%0,%1,%2,%3}, {%4,%5,%6,%7}, {%8,%9}, {%0,%1,%2,%3};"
                 : "+f"(c[0]), "+f"(c[1]), "+f"(c[2]), "+f"(c[3])
                 : "r"(a[0]), "r"(a[1]), "r"(a[2]), "r"(a[3]), "r"(b0), "r"(b1));
}
#define CP16(dst, src) \
    asm volatile("cp.async.cg.shared.global [%0], [%1], 16;" :: "r"(dst), "l"(src))
#define CP16P(dst, src, p) \
    asm volatile("{ .reg .pred q; setp.ne.b32 q, %2, 0;\n\t" \
                 "@q cp.async.cg.shared.global [%0], [%1], 16; }" \
                 :: "r"(dst), "l"(src), "r"(p))
#define CP_COMMIT  asm volatile("cp.async.commit_group;")
#define CP_WAIT1   asm volatile("cp.async.wait_group 1;")

// ---------------------------------------------------------------------------
// Fused prep
// ---------------------------------------------------------------------------
__global__ void prep_all_kernel(const float* __restrict__ X,
                                const float* __restrict__ W1, const float* __restrict__ b1,
                                const float* __restrict__ gamma, const float* __restrict__ beta,
                                const float* __restrict__ mean, const float* __restrict__ var,
                                const float* __restrict__ W2,
                                const int* __restrict__ idx32, int nx, int total4) {
    int b = blockIdx.x;
    int tid = threadIdx.x;
    if (b < 512) {
        int i = b * 256 + tid;
        int n = i >> 7;
        int k = i & 127;
        int h = n & 255;
        int grp = n >> 8;
        int srcRow;
        if (grp == 0)      srcRow = k;
        else if (grp == 1) srcRow = k + 16;
        else if (grp == 2) srcRow = 128 + k;
        else               srcRow = (k + 144) & 255;
        float s = gamma[h] * rsqrtf(var[h] + 1e-5f);
        g_WTh[i] = __float2half_rn(W1[srcRow * 256 + h] * s);
    } else if (b < 512 + nx) {
        int i = (b - 512) * 256 + tid;
        if (i < total4) {
            float4 v = *(const float4*)(X + i * 4);
            __half2* dst = (__half2*)(g_Xh + i * 4);
            dst[0] = __floats2half2_rn(v.x, v.y);
            dst[1] = __floats2half2_rn(v.z, v.w);
        }
    } else {
        if (tid < HIDDEN) {
            float s = gamma[tid] * rsqrtf(var[tid] + 1e-5f);
            g_ch[tid] = __float2half_rn(b1[tid] * s + beta[tid] - mean[tid] * s);
            g_w2h[tid] = __float2half_rn(W2[tid]);
        }
        if (tid < 32) {
            int acc = 0;
            for (int i = tid; i < 1024; i += 32) acc |= idx32[2 * i + 1];
            #pragma unroll
            for (int s = 16; s; s >>= 1) acc |= __shfl_xor_sync(0xFFFFFFFFu, acc, s);
            if (tid == 0) g_is64 = (acc == 0) ? 1 : 0;
        }
    }
}

// ---------------------------------------------------------------------------
// Persistent warp-MMA fp16 GEMM (unchanged).
// ---------------------------------------------------------------------------
#define BM 128
#define BN 128
#define SM_B    0
#define SM_A    32768
#define A_STAGE 32768
#define SM_TOTAL 98304
#define STG_STRIDE 272

__global__ __launch_bounds__(256, 2) void gemm_mma_kernel(int M) {
    extern __shared__ char smem[];
    uint32_t sb = smem_u32(smem);
    int tid = threadIdx.x;
    int lane = tid & 31;
    int wid = tid >> 5;
    int wm = wid & 3;
    int wn = wid >> 2;
    int bn = blockIdx.x * BN;
    int y = blockIdx.y;
    int NY = gridDim.y;
    int totTiles = (M + BM - 1) / BM;

    for (int s = tid; s < 2048; s += 256) {
        int row = s >> 4;
        int c = s & 15;
        uint32_t off = (uint32_t)(row * 256 + ((c ^ (row & 7)) << 4));
        CP16(sb + SM_B + off, (const char*)(g_WTh + (size_t)(bn + row) * 128 + c * 8));
    }
    CP_COMMIT;

    auto prefetchA = [&](int t, int st) {
        int bm = t * BM;
        uint32_t base = sb + SM_A + st * A_STAGE;
        for (int s = tid; s < 2048; s += 256) {
            int row = s >> 4;
            int c = s & 15;
            int gr = bm + row;
            int valid = (gr < M) ? 1 : 0;
            uint32_t off = (uint32_t)(row * 256 + ((c ^ (row & 7)) << 4));
            CP16P(base + off, (const char*)(g_Xh + (size_t)gr * 128 + c * 8), valid);
        }
        CP_COMMIT;
    };

    if (y < totTiles) prefetchA(y, 0); else CP_COMMIT;

    int aR = (lane & 15);
    int aC = lane >> 4;
    int bR = (lane & 7) + ((lane >> 4) << 3);
    int bC = (lane >> 3) & 1;

    int i = 0;
    for (int t = y; t < totTiles; t += NY, i++) {
        int tn = t + NY;
        if (tn < totTiles) prefetchA(tn, (i + 1) & 1); else CP_COMMIT;
        CP_WAIT1;
        __syncthreads();

        uint32_t aBase = sb + SM_A + (i & 1) * A_STAGE;

        float acc[2][8][4];
        #pragma unroll
        for (int mt = 0; mt < 2; mt++)
            #pragma unroll
            for (int nt = 0; nt < 8; nt++)
                #pragma unroll
                for (int q = 0; q < 4; q++) acc[mt][nt][q] = 0.f;

        #pragma unroll
        for (int ks = 0; ks < 8; ks++) {
            uint32_t a[2][4], b[4][4];
            #pragma unroll
            for (int mt = 0; mt < 2; mt++) {
                int row = wm * 32 + mt * 16 + aR;
                int ch = ks * 2 + aC;
                uint32_t off = (uint32_t)(row * 256 + ((ch ^ (row & 7)) << 4));
                ldsm_x4(a[mt][0], a[mt][1], a[mt][2], a[mt][3], aBase + off);
            }
            #pragma unroll
            for (int np = 0; np < 4; np++) {
                int row = wn * 64 + np * 16 + bR;
                int ch = ks * 2 + bC;
                uint32_t off = (uint32_t)(row * 256 + ((ch ^ (row & 7)) << 4));
                ldsm_x4(b[np][0], b[np][1], b[np][2], b[np][3], sb + SM_B + off);
            }
            #pragma unroll
            for (int mt = 0; mt < 2; mt++)
                #pragma unroll
                for (int nt = 0; nt < 8; nt++) {
                    int np = nt >> 1, qp = (nt & 1) * 2;
                    mma16816(acc[mt][nt], a[mt], b[np][qp], b[np][qp + 1]);
                }
        }

        int bm = t * BM;
        char* stg = smem + SM_A + (i & 1) * A_STAGE;
        #pragma unroll
        for (int p = 0; p < 2; p++) {
            __syncthreads();
            if ((wm >> 1) == p) {
                int lrb = (wm & 1) * 32;
                #pragma unroll
                for (int mt = 0; mt < 2; mt++)
                    #pragma unroll
                    for (int h = 0; h < 2; h++) {
                        int lr = lrb + mt * 16 + (lane >> 2) + h * 8;
                        char* rowp = stg + lr * STG_STRIDE + wn * 128 + (lane & 3) * 4;
                        #pragma unroll
                        for (int nt = 0; nt < 8; nt++)
                            *(__half2*)(rowp + nt * 16) =
                                __floats2half2_rn(acc[mt][nt][h * 2], acc[mt][nt][h * 2 + 1]);
                    }
            }
            __syncthreads();
            for (int s = tid; s < 1024; s += 256) {
                int lr = s >> 4;
                int c = s & 15;
                int gr = bm + p * 64 + lr;
                if (gr < M)
                    *(uint4*)(g_table + (size_t)gr * NCOLS + bn + c * 8) =
                        *(const uint4*)(stg + lr * STG_STRIDE + c * 16);
            }
        }
        __syncthreads();
    }
}

// ---------------------------------------------------------------------------
// Edge kernel: 2 edges/warp, half2 MLP, two 4-load waves, c/W2 in smem,
// 32-bit table offsets. Low regs -> 6 CTAs/SM for latency hiding.
// ---------------------------------------------------------------------------
__global__ __launch_bounds__(256, 6) void edge_kernel(const void* __restrict__ idx,
                                                      const float* __restrict__ b2,
                                                      float* __restrict__ out, int E) {
    __shared__ __half s_ch[HIDDEN];
    __shared__ __half s_w2[HIDDEN];
    int tid = threadIdx.x;
    if (tid < 32) {
        ((uint4*)s_ch)[tid] = ((const uint4*)g_ch)[tid];
    } else if (tid < 64) {
        ((uint4*)s_w2)[tid - 32] = ((const uint4*)g_w2h)[tid - 32];
    }
    __syncthreads();

    int lane = tid & 31;
    int e0 = blockIdx.x * 16 + (tid >> 5) * 2;
    if (e0 >= E) return;
    bool has2 = (e0 + 1 < E);
    int e1 = has2 ? e0 + 1 : e0;

    uint32_t or0, oc0, or1, oc1;
    if (g_is64) {
        const long long* p = (const long long*)idx;
        or0 = (uint32_t)p[e0] * 2048u;
        oc0 = (uint32_t)p[E + e0] * 2048u;
        or1 = (uint32_t)p[e1] * 2048u;
        oc1 = (uint32_t)p[E + e1] * 2048u;
    } else {
        const int* p = (const int*)idx;
        or0 = (uint32_t)p[e0] * 2048u;
        oc0 = (uint32_t)p[E + e0] * 2048u;
        or1 = (uint32_t)p[e1] * 2048u;
        oc1 = (uint32_t)p[E + e1] * 2048u;
    }
    const char* tb = (const char*)g_table;
    uint32_t lo = (uint32_t)lane * 16u;   // 16B per lane

    const __half2* ch = (const __half2*)s_ch + lane * 4;
    const __half2* wh = (const __half2*)s_w2 + lane * 4;
    const __half2 zero = __float2half2_rn(0.f);
    __half2 accA = zero, accB = zero;

    // ---- wave 1: p1 streams (seg0 row + seg1 col)
    {
        uint4 a0 = *(const uint4*)(tb + or0 + lo);
        uint4 b1 = *(const uint4*)(tb + oc0 + 1024u + lo);
        uint4 d0 = *(const uint4*)(tb + or1 + lo);
        uint4 f1 = *(const uint4*)(tb + oc1 + 1024u + lo);
        const __half2* pa = (const __half2*)&a0;
        const __half2* pb = (const __half2*)&b1;
        const __half2* pd = (const __half2*)&d0;
        const __half2* pf = (const __half2*)&f1;
        #pragma unroll
        for (int j = 0; j < 4; j++) {
            __half2 z = __hadd2(__hadd2(pa[j], pb[j]), ch[j]);
            accA = __hfma2(__hmax2(z, zero), wh[j], accA);
            __half2 y = __hadd2(__hadd2(pd[j], pf[j]), ch[j]);
            accB = __hfma2(__hmax2(y, zero), wh[j], accB);
        }
    }
    // ---- wave 2: p2 streams (seg2 row + seg3 col)
    {
        uint4 a2 = *(const uint4*)(tb + or0 + 512u + lo);
        uint4 b3 = *(const uint4*)(tb + oc0 + 1536u + lo);
        uint4 d2 = *(const uint4*)(tb + or1 + 512u + lo);
        uint4 f3 = *(const uint4*)(tb + oc1 + 1536u + lo);
        const __half2* pa = (const __half2*)&a2;
        const __half2* pb = (const __half2*)&b3;
        const __half2* pd = (const __half2*)&d2;
        const __half2* pf = (const __half2*)&f3;
        #pragma unroll
        for (int j = 0; j < 4; j++) {
            __half2 z = __hadd2(__hadd2(pa[j], pb[j]), ch[j]);
            accA = __hfma2(__hmax2(z, zero), wh[j], accA);
            __half2 y = __hadd2(__hadd2(pd[j], pf[j]), ch[j]);
            accB = __hfma2(__hmax2(y, zero), wh[j], accB);
        }
    }

    float2 fA = __half22float2(accA);
    float2 fB = __half22float2(accB);
    float sA = fA.x + fA.y;
    float sB = fB.x + fB.y;
    #pragma unroll
    for (int s = 16; s; s >>= 1) {
        sA += __shfl_xor_sync(0xFFFFFFFFu, sA, s);
        sB += __shfl_xor_sync(0xFFFFFFFFu, sB, s);
    }

    if (lane == 0) {
        float bb = b2[0];
        float x = sA * 0.5f + bb;
        out[e0] = 1.f / (1.f + expf(-x));
        if (has2) {
            float x2 = sB * 0.5f + bb;
            out[e0 + 1] = 1.f / (1.f + expf(-x2));
        }
    }
}

// ---------------------------------------------------------------------------
extern "C" void kernel_launch(void* const* d_in, const int* in_sizes, int n_in,
                              void* d_out, int out_size) {
    const float* node_feat = (const float*)d_in[0];
    const void*  eidx      = d_in[1];
    const float* W1        = (const float*)d_in[2];
    const float* b1        = (const float*)d_in[3];
    const float* gamma     = (const float*)d_in[4];
    const float* beta      = (const float*)d_in[5];
    const float* mean      = (const float*)d_in[6];
    const float* var       = (const float*)d_in[7];
    const float* W2        = (const float*)d_in[8];
    const float* b2        = (const float*)d_in[9];
    float* out = (float*)d_out;

    int M = in_sizes[0] / NODE_DIM;   // 50000
    int E = out_size;                 // 300000

    cudaFuncSetAttribute(gemm_mma_kernel, cudaFuncAttributeMaxDynamicSharedMemorySize, SM_TOTAL);

    int total4 = M * NODE_DIM / 4;
    int nx = (total4 + 255) / 256;
    prep_all_kernel<<<512 + nx + 1, 256>>>(node_feat, W1, b1, gamma, beta, mean, var, W2,
                                           (const int*)eidx, nx, total4);

    dim3 ggrid(NCOLS / BN, 36);   // 288 persistent CTAs, 2/SM
    gemm_mma_kernel<<<ggrid, 256, SM_TOTAL>>>(M);

    edge_kernel<<<(E + 15) / 16, 256>>>(eidx, b2, out, E);
}